// round 4
// baseline (speedup 1.0000x reference)
#include <cuda_runtime.h>
#include <cstdint>

// ============================================================================
// SIREN fused inference, register-chained mma.sync bf16 (sm_103-safe PTX).
// Each warp owns 16 rows x full 256 cols; mma C-fragment layout == next
// layer's A-fragment layout, so activations stay warp-private (regs + a
// thread-private SMEM spill area). Weights are pre-packed in per-lane
// fragment order and read with one LDG.128 per fragment (L1/L2 broadcast).
// No __syncthreads in the main loop: warps stagger freely.
// ============================================================================

#define THREADS    256
#define M_TILE     128
#define N_POINTS   1048576
#define GRID_CTAS  (N_POINTS / M_TILE)      // 8192

// --- SMEM layout (bytes) ---
// A hi/lo slots: 8 warps x 64 slots x 32 lanes x 8B = 131072
#define AB_OFF     0
#define W0S_OFF    131072                    // 768 floats
#define B0S_OFF    (W0S_OFF + 3072)          // 256 floats
#define BIAS_OFF   (B0S_OFF + 1024)          // 1024 floats (b1..b4)
#define WFS_OFF    (BIAS_OFF + 4096)         // 256 floats
#define SMEM_TOTAL (WFS_OFF + 1024)          // 140288

// Fragment-packed weights: [layer(4)][kk(16)][j(32)][lane(32)] -> uint4
// uint4 = { bh0, bh1, bl0, bl1 } for B-fragment (j,kk) of that lane.
__device__ __align__(128) uint4 g_wfrag[4 * 16 * 32 * 32];

// ---------------------------------------------------------------------------
// helpers
// ---------------------------------------------------------------------------
__device__ __forceinline__ uint32_t smem_u32(const void* p) {
    uint32_t a;
    asm("{ .reg .u64 t; cvta.to.shared.u64 t, %1; cvt.u32.u64 %0, t; }"
        : "=r"(a) : "l"(p));
    return a;
}

#define MMA_BF16(d, a0, a1, a2, a3, b0, b1)                                    \
    asm volatile("mma.sync.aligned.m16n8k16.row.col.f32.bf16.bf16.f32 "        \
        "{%0,%1,%2,%3}, {%4,%5,%6,%7}, {%8,%9}, {%0,%1,%2,%3};"                \
        : "+f"((d)[0]), "+f"((d)[1]), "+f"((d)[2]), "+f"((d)[3])               \
        : "r"(a0), "r"(a1), "r"(a2), "r"(a3), "r"(b0), "r"(b1))

#define STSV2(addr, h, l) \
    asm volatile("st.shared.v2.u32 [%0], {%1,%2};" :: "r"(addr), "r"(h), "r"(l) : "memory")
#define LDSV2(h, l, addr) \
    asm volatile("ld.shared.v2.u32 {%0,%1}, [%2];" : "=r"(h), "=r"(l) : "r"(addr) : "memory")

// exact truncation split of two fp32: hi = [h0.hi16 | h1.hi16] (bf16x2),
// lo = bf16x2 of the exact residuals.
__device__ __forceinline__ void split_pack(float h0, float h1,
                                           uint32_t& hiw, uint32_t& low) {
    uint32_t u0 = __float_as_uint(h0), u1 = __float_as_uint(h1);
    hiw = __byte_perm(u0, u1, 0x7632);
    float l0 = h0 - __uint_as_float(u0 & 0xFFFF0000u);
    float l1 = h1 - __uint_as_float(u1 & 0xFFFF0000u);
    asm("cvt.rn.bf16x2.f32 %0, %1, %2;" : "=r"(low) : "f"(l1), "f"(l0));
}

// ---------------------------------------------------------------------------
// prep: W1..W4 fp32 [256n,256k] -> per-lane B-fragment order, bf16 hi/lo
// B frag (m16n8k16): b0 = { W[n=8j+g][k=16kk+2t], W[..][k+1] },
//                    b1 = { W[n][16kk+8+2t], W[n][..+9] }   (g=lane>>2,t=lane&3)
// ---------------------------------------------------------------------------
__global__ void prep_weights(const float* __restrict__ W1, const float* __restrict__ W2,
                             const float* __restrict__ W3, const float* __restrict__ W4) {
    int idx = blockIdx.x * blockDim.x + threadIdx.x;   // 65536
    int lane = idx & 31;
    int j    = (idx >> 5) & 31;
    int kk   = (idx >> 10) & 15;
    int l    = idx >> 14;
    const float* W = (l == 0) ? W1 : (l == 1) ? W2 : (l == 2) ? W3 : W4;
    int g = lane >> 2, t = lane & 3;
    const float* wr = W + (8 * j + g) * 256 + 16 * kk + 2 * t;
    uint32_t bh0, bl0, bh1, bl1;
    split_pack(wr[0], wr[1], bh0, bl0);
    split_pack(wr[8], wr[9], bh1, bl1);
    g_wfrag[idx] = make_uint4(bh0, bh1, bl0, bl1);
}

// ---------------------------------------------------------------------------
// main kernel
// ---------------------------------------------------------------------------
__global__ void __launch_bounds__(THREADS, 1)
siren_chained_kernel(const float* __restrict__ xyt, const float* __restrict__ W0,
                     const float* __restrict__ b0, const float* __restrict__ b1,
                     const float* __restrict__ b2, const float* __restrict__ b3,
                     const float* __restrict__ b4, const float* __restrict__ Wf,
                     const float* __restrict__ bfp, float* __restrict__ out) {
    extern __shared__ char smem[];
    const uint32_t sb = smem_u32(smem);
    const int tid = threadIdx.x;
    const int lane = tid & 31;
    const int wid = tid >> 5;
    const int g = lane >> 2;
    const int t = lane & 3;

    float* W0s  = (float*)(smem + W0S_OFF);
    float* b0s  = (float*)(smem + B0S_OFF);
    float* bias = (float*)(smem + BIAS_OFF);
    float* Wfs  = (float*)(smem + WFS_OFF);
    for (int i = tid; i < 768; i += THREADS) W0s[i] = W0[i];
    if (tid < 256) {
        b0s[tid] = b0[tid];
        bias[tid]       = b1[tid];
        bias[256 + tid] = b2[tid];
        bias[512 + tid] = b3[tid];
        bias[768 + tid] = b4[tid];
        Wfs[tid] = Wf[tid];
    }
    __syncthreads();     // only barrier in the kernel

    const float bfv = bfp[0];

    // thread-private A hi/lo slot base: slot s at ab + s*256 (8B per lane)
    const uint32_t ab = sb + AB_OFF + (uint32_t)wid * 16384u + (uint32_t)lane * 8u;

    const int r0 = blockIdx.x * M_TILE + wid * 16 + g;
    const int r1 = r0 + 8;

    // ---- first layer (SIMT): sin(30*(x@W0^T+b0)) -> A slots ----
    {
        float x00 = xyt[3 * r0], x01 = xyt[3 * r0 + 1], x02 = xyt[3 * r0 + 2];
        float x10 = xyt[3 * r1], x11 = xyt[3 * r1 + 1], x12 = xyt[3 * r1 + 2];
#pragma unroll
        for (int j = 0; j < 32; j++) {
            int n0 = 8 * j + 2 * t;
            const float* w0a = W0s + 3 * n0;
            float c0 = w0a[0], c1 = w0a[1], c2 = w0a[2];
            float d0 = w0a[3], d1 = w0a[4], d2 = w0a[5];
            float bb0 = b0s[n0], bb1 = b0s[n0 + 1];
            float z00 = fmaf(x00, c0, fmaf(x01, c1, fmaf(x02, c2, bb0)));
            float z01 = fmaf(x00, d0, fmaf(x01, d1, fmaf(x02, d2, bb1)));
            float z10 = fmaf(x10, c0, fmaf(x11, c1, fmaf(x12, c2, bb0)));
            float z11 = fmaf(x10, d0, fmaf(x11, d1, fmaf(x12, d2, bb1)));
            uint32_t h, lo;
            split_pack(__sinf(30.0f * z00), __sinf(30.0f * z01), h, lo);
            STSV2(ab + (uint32_t)(2 * j) * 256u, h, lo);
            split_pack(__sinf(30.0f * z10), __sinf(30.0f * z11), h, lo);
            STSV2(ab + (uint32_t)(2 * j + 1) * 256u, h, lo);
        }
    }

    // ---- 4 hidden layers, warp-independent ----
#pragma unroll 1
    for (int l = 0; l < 4; l++) {
        float acc[32][4];
#pragma unroll
        for (int j = 0; j < 32; j++) {
            acc[j][0] = 0.0f; acc[j][1] = 0.0f; acc[j][2] = 0.0f; acc[j][3] = 0.0f;
        }

        const uint4* __restrict__ wl = g_wfrag + ((size_t)l << 14) + lane;

#pragma unroll
        for (int kk = 0; kk < 16; kk++) {
            uint32_t ah0, al0, ah1, al1, ah2, al2, ah3, al3;
            LDSV2(ah0, al0, ab + (uint32_t)(4 * kk + 0) * 256u);
            LDSV2(ah1, al1, ab + (uint32_t)(4 * kk + 1) * 256u);
            LDSV2(ah2, al2, ab + (uint32_t)(4 * kk + 2) * 256u);
            LDSV2(ah3, al3, ab + (uint32_t)(4 * kk + 3) * 256u);
            const uint4* __restrict__ wk = wl + (kk << 10);
#pragma unroll
            for (int j = 0; j < 32; j++) {
                uint4 b = __ldg(wk + (j << 5));
                MMA_BF16(acc[j], ah0, ah1, ah2, ah3, b.x, b.y);   // hi*hi
                MMA_BF16(acc[j], al0, al1, al2, al3, b.x, b.y);   // lo*hi
                MMA_BF16(acc[j], ah0, ah1, ah2, ah3, b.z, b.w);   // hi*lo
            }
        }

        if (l < 3) {
            const float* bs = bias + l * 256;
#pragma unroll
            for (int j = 0; j < 32; j++) {
                int n0 = 8 * j + 2 * t;
                float bb0 = bs[n0], bb1 = bs[n0 + 1];
                uint32_t h, lo;
                split_pack(__sinf(acc[j][0] + bb0), __sinf(acc[j][1] + bb1), h, lo);
                STSV2(ab + (uint32_t)(2 * j) * 256u, h, lo);
                split_pack(__sinf(acc[j][2] + bb0), __sinf(acc[j][3] + bb1), h, lo);
                STSV2(ab + (uint32_t)(2 * j + 1) * 256u, h, lo);
            }
        } else {
            const float* bs = bias + 768;
            float p0 = 0.0f, p1 = 0.0f;
#pragma unroll
            for (int j = 0; j < 32; j++) {
                int n0 = 8 * j + 2 * t;
                float bb0 = bs[n0], bb1 = bs[n0 + 1];
                float wf0 = Wfs[n0], wf1 = Wfs[n0 + 1];
                p0 = fmaf(__sinf(acc[j][0] + bb0), wf0, p0);
                p0 = fmaf(__sinf(acc[j][1] + bb1), wf1, p0);
                p1 = fmaf(__sinf(acc[j][2] + bb0), wf0, p1);
                p1 = fmaf(__sinf(acc[j][3] + bb1), wf1, p1);
            }
            p0 += __shfl_xor_sync(0xffffffffu, p0, 1);
            p0 += __shfl_xor_sync(0xffffffffu, p0, 2);
            p1 += __shfl_xor_sync(0xffffffffu, p1, 1);
            p1 += __shfl_xor_sync(0xffffffffu, p1, 2);
            if (t == 0) {
                out[r0] = p0 + bfv;
                out[r1] = p1 + bfv;
            }
        }
    }
}

// ---------------------------------------------------------------------------
// kernel_launch
// ---------------------------------------------------------------------------
extern "C" void kernel_launch(void* const* d_in, const int* in_sizes, int n_in,
                              void* d_out, int out_size) {
    const float* xyt = (const float*)d_in[0];
    const float* W0  = (const float*)d_in[1];
    const float* b0  = (const float*)d_in[2];
    const float* W1  = (const float*)d_in[3];
    const float* b1  = (const float*)d_in[4];
    const float* W2  = (const float*)d_in[5];
    const float* b2  = (const float*)d_in[6];
    const float* W3  = (const float*)d_in[7];
    const float* b3  = (const float*)d_in[8];
    const float* W4  = (const float*)d_in[9];
    const float* b4  = (const float*)d_in[10];
    const float* Wf  = (const float*)d_in[11];
    const float* bf  = (const float*)d_in[12];
    float* out = (float*)d_out;
    (void)in_sizes; (void)n_in; (void)out_size;

    cudaFuncSetAttribute(siren_chained_kernel,
                         cudaFuncAttributeMaxDynamicSharedMemorySize, SMEM_TOTAL);

    prep_weights<<<256, 256>>>(W1, W2, W3, W4);
    siren_chained_kernel<<<GRID_CTAS, THREADS, SMEM_TOTAL>>>(
        xyt, W0, b0, b1, b2, b3, b4, Wf, bf, out);
}